// round 2
// baseline (speedup 1.0000x reference)
#include <cuda_runtime.h>
#include <cstdint>
#include <cstddef>

#define NVARS 100000
#define NCLS  420000
#define NLIT  200000
#define NNZT  1260000
#define NGR   32
#define EPSN  1e-6f

// ------------------------- device scratch (no allocs) -------------------------
__device__ __align__(16) float g_var[(size_t)NVARS * 64];
__device__ __align__(16) float g_clauses[(size_t)NCLS * 64];   // unscaled new_clause state
__device__ __align__(16) float g_query[(size_t)NVARS * 64];
__device__ __align__(16) float g_cl[(size_t)NCLS * 64];        // exp(-cv)
__device__ __align__(16) float g_hcm[(size_t)NCLS * 128];      // cm hidden / co hidden
__device__ __align__(16) float g_cdata[(size_t)NCLS * 128];    // clause_unit then clause_data
__device__ __align__(16) float g_unit[(size_t)NVARS * 256];
__device__ __align__(16) float g_h1[(size_t)NVARS * 128];      // v1 [V,68] then ug hidden1
__device__ __align__(16) float g_h2[(size_t)NVARS * 128];
__device__ __align__(16) float g_nv[(size_t)NVARS * 64];       // vq hidden / ug out
__device__ float g_dw[NLIT];
__device__ float g_vdw[NVARS];
__device__ int   g_litdeg[NLIT];
__device__ int   g_csroff[NLIT + 1];
__device__ int   g_cursor[NLIT];
__device__ int   g_csrc[NNZT];
__device__ int   g_vstart[NGR + 1];
__device__ int   g_cstart[NGR + 1];
__device__ float g_gsum[NGR * 64];
__device__ float g_gss[NGR];

// ------------------------- Threefry-2x32 (JAX exact) -------------------------
__host__ __device__ inline void tf_block(uint32_t k0, uint32_t k1, uint32_t x0, uint32_t x1,
                                         uint32_t& o0, uint32_t& o1) {
    uint32_t k2 = k0 ^ k1 ^ 0x1BD11BDAu;
    x0 += k0; x1 += k1;
#define TFR(r) { x0 += x1; x1 = (x1 << (r)) | (x1 >> (32 - (r))); x1 ^= x0; }
    TFR(13) TFR(15) TFR(26) TFR(6)  x0 += k1; x1 += k2 + 1u;
    TFR(17) TFR(29) TFR(16) TFR(24) x0 += k2; x1 += k0 + 2u;
    TFR(13) TFR(15) TFR(26) TFR(6)  x0 += k0; x1 += k1 + 3u;
    TFR(17) TFR(29) TFR(16) TFR(24) x0 += k1; x1 += k2 + 4u;
    TFR(13) TFR(15) TFR(26) TFR(6)  x0 += k2; x1 += k0 + 5u;
#undef TFR
    o0 = x0; o1 = x1;
}

// XLA ErfInv32 (Giles polynomial) — matches lax.erf_inv f32 lowering
__device__ __forceinline__ float erfinv_f32(float x) {
    float w = -log1pf(-x * x);
    float p;
    if (w < 5.0f) {
        w -= 2.5f;
        p = 2.81022636e-08f;
        p = fmaf(p, w, 3.43273939e-07f);
        p = fmaf(p, w, -3.5233877e-06f);
        p = fmaf(p, w, -4.39150654e-06f);
        p = fmaf(p, w, 0.00021858087f);
        p = fmaf(p, w, -0.00125372503f);
        p = fmaf(p, w, -0.00417768164f);
        p = fmaf(p, w, 0.246640727f);
        p = fmaf(p, w, 1.50140941f);
    } else {
        w = sqrtf(w) - 3.0f;
        p = -0.000200214257f;
        p = fmaf(p, w, 0.000100950558f);
        p = fmaf(p, w, 0.00134934322f);
        p = fmaf(p, w, -0.00367342844f);
        p = fmaf(p, w, 0.00573950773f);
        p = fmaf(p, w, -0.0076224613f);
        p = fmaf(p, w, 0.00943887047f);
        p = fmaf(p, w, 1.00167406f);
        p = fmaf(p, w, 2.83297682f);
    }
    return p * x;
}

// normal(key, .)[i] via partitionable random_bits: bits = o0^o1 of block(key,(0,i))
__device__ __forceinline__ float jr_normal(uint32_t k0, uint32_t k1, uint32_t idx) {
    uint32_t a, b;
    tf_block(k0, k1, 0u, idx, a, b);
    uint32_t bits = a ^ b;
    float f = __uint_as_float(0x3F800000u | (bits >> 9)) - 1.0f;
    float u = fmaxf(fmaf(f, 2.0f, -0.99999994f), -0.99999994f);
    return 1.41421356f * erfinv_f32(u);
}

// ------------------------- GEMM: Y[M,N] = act(X[M,K] @ W[K,N] + b) -------------------------
template<int K, int N, bool RELU>
__global__ __launch_bounds__(256)
void k_gemm(const float* __restrict__ X, const float* __restrict__ W,
            const float* __restrict__ bias, float* __restrict__ Y, int M) {
    constexpr int TN = N / 16;
    __shared__ float Xs[16][68];
    __shared__ float Ws[16][N];
    int t = threadIdx.x;
    int m0 = blockIdx.x * 64;
    int tx = t & 15, ty = t >> 4;
    float acc[4][TN];
#pragma unroll
    for (int i = 0; i < 4; i++)
#pragma unroll
        for (int j = 0; j < TN; j++) acc[i][j] = 0.f;
    float bs[TN];
#pragma unroll
    for (int j = 0; j < TN; j++) bs[j] = bias[tx * TN + j];

    int r = t >> 2, kg = t & 3;
    const float* xrow = X + (size_t)(m0 + r) * K;
    bool rok = (m0 + r) < M;
    constexpr int KT = (K + 15) / 16;
    constexpr int NF4 = N / 4;
    for (int kt = 0; kt < KT; kt++) {
        int k0 = kt * 16;
        float4 xv = make_float4(0.f, 0.f, 0.f, 0.f);
        int kk = k0 + kg * 4;
        if (rok && kk < K) xv = *(const float4*)(xrow + kk);
        Xs[kg * 4 + 0][r] = xv.x;
        Xs[kg * 4 + 1][r] = xv.y;
        Xs[kg * 4 + 2][r] = xv.z;
        Xs[kg * 4 + 3][r] = xv.w;
#pragma unroll
        for (int q = t; q < 16 * NF4; q += 256) {
            int k = q / NF4, n4 = q % NF4;
            float4 wv = make_float4(0.f, 0.f, 0.f, 0.f);
            if (k0 + k < K) wv = *(const float4*)(W + (size_t)(k0 + k) * N + n4 * 4);
            *((float4*)&Ws[k][0] + n4) = wv;
        }
        __syncthreads();
#pragma unroll
        for (int k = 0; k < 16; k++) {
            float4 a = *(const float4*)&Xs[k][ty * 4];
            float b[TN];
#pragma unroll
            for (int j4 = 0; j4 < TN / 4; j4++) {
                float4 w4 = *((const float4*)&Ws[k][tx * TN] + j4);
                b[j4 * 4 + 0] = w4.x; b[j4 * 4 + 1] = w4.y;
                b[j4 * 4 + 2] = w4.z; b[j4 * 4 + 3] = w4.w;
            }
#pragma unroll
            for (int j = 0; j < TN; j++) {
                acc[0][j] = fmaf(a.x, b[j], acc[0][j]);
                acc[1][j] = fmaf(a.y, b[j], acc[1][j]);
                acc[2][j] = fmaf(a.z, b[j], acc[2][j]);
                acc[3][j] = fmaf(a.w, b[j], acc[3][j]);
            }
        }
        __syncthreads();
    }
#pragma unroll
    for (int i = 0; i < 4; i++) {
        int row = m0 + ty * 4 + i;
        if (row < M) {
#pragma unroll
            for (int j4 = 0; j4 < TN / 4; j4++) {
                float4 o;
                o.x = acc[i][j4 * 4 + 0] + bs[j4 * 4 + 0];
                o.y = acc[i][j4 * 4 + 1] + bs[j4 * 4 + 1];
                o.z = acc[i][j4 * 4 + 2] + bs[j4 * 4 + 2];
                o.w = acc[i][j4 * 4 + 3] + bs[j4 * 4 + 3];
                if (RELU) {
                    o.x = fmaxf(o.x, 0.f); o.y = fmaxf(o.y, 0.f);
                    o.z = fmaxf(o.z, 0.f); o.w = fmaxf(o.w, 0.f);
                }
                *((float4*)(Y + (size_t)row * N + tx * TN) + j4) = o;
            }
        }
    }
}

// ------------------------- precompute kernels -------------------------
__global__ void k_hist(const int* __restrict__ lit_idx) {
    int e = blockIdx.x * blockDim.x + threadIdx.x;
    if (e < NNZT) atomicAdd(&g_litdeg[lit_idx[e]], 1);
}

__global__ void k_scan() {  // single block 1024, exclusive scan of g_litdeg -> g_csroff
    __shared__ int warps[32];
    __shared__ int s_carry;
    int t = threadIdx.x;
    if (t == 0) s_carry = 0;
    __syncthreads();
    const int NCHUNK = (NLIT + 1023) / 1024;
    for (int ch = 0; ch < NCHUNK; ch++) {
        int idx = ch * 1024 + t;
        int v = (idx < NLIT) ? g_litdeg[idx] : 0;
        int x = v;
#pragma unroll
        for (int o = 1; o < 32; o <<= 1) {
            int y = __shfl_up_sync(0xffffffffu, x, o);
            if ((t & 31) >= o) x += y;
        }
        if ((t & 31) == 31) warps[t >> 5] = x;
        __syncthreads();
        if (t < 32) {
            int y = warps[t];
#pragma unroll
            for (int o = 1; o < 32; o <<= 1) {
                int z = __shfl_up_sync(0xffffffffu, y, o);
                if (t >= o) y += z;
            }
            warps[t] = y;
        }
        __syncthreads();
        int incl = x + ((t >= 32) ? warps[(t >> 5) - 1] : 0);
        int excl = incl - v;
        if (idx < NLIT) g_csroff[idx] = s_carry + excl;
        int total = warps[31];
        __syncthreads();
        if (t == 0) s_carry += total;
        __syncthreads();
    }
    if (t == 0) g_csroff[NLIT] = s_carry;
}

__global__ void k_dw() {
    int i = blockIdx.x * blockDim.x + threadIdx.x;
    if (i < NLIT) {
        g_dw[i] = rsqrtf(fmaxf((float)g_litdeg[i], 1.f));
        g_cursor[i] = 0;
    }
    if (i < NVARS)
        g_vdw[i] = 4.f * rsqrtf(fmaxf((float)(g_litdeg[i] + g_litdeg[i + NVARS]), 1.f));
}

__global__ void k_fill(const int* __restrict__ lit_idx, const int* __restrict__ clause_idx) {
    int e = blockIdx.x * blockDim.x + threadIdx.x;
    if (e >= NNZT) return;
    int l = lit_idx[e];
    int pos = atomicAdd(&g_cursor[l], 1);
    g_csrc[g_csroff[l] + pos] = clause_idx[e];
}

__global__ void k_sortrows() {  // determinism hygiene (atomic fill order varies)
    int l = blockIdx.x * blockDim.x + threadIdx.x;
    if (l >= NLIT) return;
    int b = g_csroff[l], n = g_csroff[l + 1] - b;
    if (n <= 1 || n > 48) return;
    int a[48];
    for (int i = 0; i < n; i++) a[i] = g_csrc[b + i];
    for (int i = 1; i < n; i++) {
        int key = a[i], j = i - 1;
        while (j >= 0 && a[j] > key) { a[j + 1] = a[j]; j--; }
        a[j + 1] = key;
    }
    for (int i = 0; i < n; i++) g_csrc[b + i] = a[i];
}

__global__ void k_starts(const int* __restrict__ vgid, const int* __restrict__ cgid) {
    int g = threadIdx.x;
    if (g > NGR) return;
    int lo = 0, hi = NVARS;
    while (lo < hi) { int mid = (lo + hi) >> 1; if (vgid[mid] < g) lo = mid + 1; else hi = mid; }
    g_vstart[g] = lo;
    lo = 0; hi = NCLS;
    while (lo < hi) { int mid = (lo + hi) >> 1; if (cgid[mid] < g) lo = mid + 1; else hi = mid; }
    g_cstart[g] = lo;
}

__global__ void k_initones() {
    size_t i = (size_t)blockIdx.x * blockDim.x + threadIdx.x;
    size_t nv = (size_t)NVARS * 64, nc = (size_t)NCLS * 64;
    if (i < nv) g_var[i] = 1.f;
    if (i < nc) g_clauses[i] = 1.f;
}

// ------------------------- per-round kernels -------------------------
__global__ void k_v1(uint32_t k0, uint32_t k1) {  // v1 = [variables, noise] into g_h1 [V,68]
    int idx = blockIdx.x * blockDim.x + threadIdx.x;
    if (idx >= NVARS * 17) return;
    int v = idx / 17, c4 = idx % 17;
    if (c4 < 16) {
        float4 val = *(const float4*)(g_var + (size_t)v * 64 + c4 * 4);
        *(float4*)(g_h1 + (size_t)v * 68 + c4 * 4) = val;
    } else {
        float4 o;
        o.x = jr_normal(k0, k1, (uint32_t)(v * 4 + 0));
        o.y = jr_normal(k0, k1, (uint32_t)(v * 4 + 1));
        o.z = jr_normal(k0, k1, (uint32_t)(v * 4 + 2));
        o.w = jr_normal(k0, k1, (uint32_t)(v * 4 + 3));
        *(float4*)(g_h1 + (size_t)v * 68 + 64) = o;
    }
}

__global__ void k_cv(const int* __restrict__ lit_idx) {  // cl = exp(-sum softplus(+/-q))
    int t = threadIdx.x;
    int c = blockIdx.x * 4 + (t >> 6);
    int f = t & 63;
    if (c >= NCLS) return;
    float s = 0.f;
#pragma unroll
    for (int j = 0; j < 3; j++) {
        int l = lit_idx[3 * c + j];
        float sgn = 1.f; int v = l;
        if (l >= NVARS) { v = l - NVARS; sgn = -1.f; }
        float x = sgn * g_query[(size_t)v * 64 + f];
        s += fmaxf(x, 0.f) + log1pf(expf(-fabsf(x)));
    }
    g_cl[(size_t)c * 64 + f] = expf(-s);
}

__global__ void k_gradunit() {  // unit cols 0..127: variables_grad | variables
    int t = threadIdx.x;
    int v = blockIdx.x * 4 + (t >> 6);
    int f = t & 63;
    if (v >= NVARS) return;
    float S1 = 0.f, S2 = 0.f;
    int b0 = g_csroff[v], e0 = g_csroff[v + 1];
    for (int i = b0; i < e0; i++) S1 += g_cl[(size_t)g_csrc[i] * 64 + f];
    int b1 = g_csroff[NVARS + v], e1 = g_csroff[NVARS + v + 1];
    for (int i = b1; i < e1; i++) S2 += g_cl[(size_t)g_csrc[i] * 64 + f];
    float q = g_query[(size_t)v * 64 + f];
    float sp = 1.f / (1.f + expf(-q));
    float sn = 1.f / (1.f + expf(q));
    float qg = fmaf(-S1, sp, S2 * sn);
    g_unit[(size_t)v * 256 + f] = qg * g_vdw[v];
    g_unit[(size_t)v * 256 + 64 + f] = g_var[(size_t)v * 64 + f];
}

__global__ void k_VL() {  // unit cols 128..255: variables_loss halves
    int t = threadIdx.x;
    int v = blockIdx.x * 4 + (t >> 6);
    int f = t & 63;
    if (v >= NVARS) return;
    float T1 = 0.f, T2 = 0.f;
    int b0 = g_csroff[v], e0 = g_csroff[v + 1];
    for (int i = b0; i < e0; i++) T1 += g_cdata[(size_t)g_csrc[i] * 128 + f];
    int b1 = g_csroff[NVARS + v], e1 = g_csroff[NVARS + v + 1];
    for (int i = b1; i < e1; i++) T2 += g_cdata[(size_t)g_csrc[i] * 128 + f];
    g_unit[(size_t)v * 256 + 128 + f] = T1 * g_dw[v];
    g_unit[(size_t)v * 256 + 192 + f] = T2 * g_dw[v + NVARS];
}

__global__ void k_cubuild(float cscale) {  // clause_unit = [cscale*clauses, 4*cl]
    int i4 = blockIdx.x * blockDim.x + threadIdx.x;
    if (i4 >= NCLS * 32) return;
    int c = i4 >> 5, f4 = i4 & 31;
    float4 o;
    if (f4 < 16) {
        float4 v = *(const float4*)(g_clauses + (size_t)c * 64 + f4 * 4);
        o.x = v.x * cscale; o.y = v.y * cscale; o.z = v.z * cscale; o.w = v.w * cscale;
    } else {
        float4 v = *(const float4*)(g_cl + (size_t)c * 64 + (f4 - 16) * 4);
        o.x = 4.f * v.x; o.y = 4.f * v.y; o.z = 4.f * v.z; o.w = 4.f * v.w;
    }
    *(float4*)(g_cdata + (size_t)c * 128 + f4 * 4) = o;
}

// ------------------------- PairNorm (3 passes) -------------------------
template<bool CL>
__global__ void k_pnA(const int* __restrict__ gid) {
    const float* x = CL ? (g_cdata + 64) : g_nv;
    const int stride = CL ? 128 : 64;
    const int M = CL ? NCLS : NVARS;
    int G = gridDim.x;
    int chunk = (M + G - 1) / G;
    int start = blockIdx.x * chunk, end = min(M, start + chunk);
    int f = threadIdx.x & 63, rl = threadIdx.x >> 6;
    float acc = 0.f; int curg = -1;
    for (int r = start + rl; r < end; r += 4) {
        int g = gid[r];
        if (g != curg) {
            if (curg >= 0) atomicAdd(&g_gsum[curg * 64 + f], acc);
            acc = 0.f; curg = g;
        }
        acc += x[(size_t)r * stride + f];
    }
    if (curg >= 0) atomicAdd(&g_gsum[curg * 64 + f], acc);
}

template<bool CL>
__global__ void k_pnB(const int* __restrict__ gid) {
    const float* x = CL ? (g_cdata + 64) : g_nv;
    const int stride = CL ? 128 : 64;
    const int M = CL ? NCLS : NVARS;
    const int* starts = CL ? g_cstart : g_vstart;
    int G = gridDim.x;
    int chunk = (M + G - 1) / G;
    int start = blockIdx.x * chunk, end = min(M, start + chunk);
    int w = threadIdx.x >> 5, lane = threadIdx.x & 31;
    float acc = 0.f; int curg = -1;
    for (int r = start + w; r < end; r += 8) {
        int g = gid[r];
        float cnt = fmaxf((float)(starts[g + 1] - starts[g]), 1.f);
        float m1 = g_gsum[g * 64 + lane] / cnt;
        float m2 = g_gsum[g * 64 + lane + 32] / cnt;
        float d1 = x[(size_t)r * stride + lane] - m1;
        float d2 = x[(size_t)r * stride + lane + 32] - m2;
        float p = d1 * d1 + d2 * d2;
#pragma unroll
        for (int o = 16; o > 0; o >>= 1) p += __shfl_down_sync(0xffffffffu, p, o);
        if (lane == 0) {
            p *= (1.f / 64.f);
            if (g != curg) {
                if (curg >= 0) atomicAdd(&g_gss[curg], acc);
                acc = 0.f; curg = g;
            }
            acc += p;
        }
    }
    if (lane == 0 && curg >= 0) atomicAdd(&g_gss[curg], acc);
}

template<bool CL>
__global__ void k_pnC(const int* __restrict__ gid, float oldscale) {
    const float* x = CL ? (g_cdata + 64) : g_nv;
    const int stride = CL ? 128 : 64;
    const int M = CL ? NCLS : NVARS;
    const int* starts = CL ? g_cstart : g_vstart;
    float* out = CL ? g_clauses : g_var;
    int i = blockIdx.x * blockDim.x + threadIdx.x;
    if (i >= M * 64) return;
    int r = i >> 6, f = i & 63;
    int g = gid[r];
    float cnt = fmaxf((float)(starts[g + 1] - starts[g]), 1.f);
    float mean = g_gsum[g * 64 + f] / cnt;
    float var = g_gss[g] / cnt;
    float val = 0.25f * (x[(size_t)r * stride + f] - mean) * rsqrtf(var + EPSN);
    out[(size_t)r * 64 + f] = val + oldscale * out[(size_t)r * 64 + f];
}

// ------------------------- final logits + noise + sigmoid -------------------------
__global__ void k_logits(const float* __restrict__ W1, const float* __restrict__ b1,
                         float* __restrict__ out, uint32_t k0, uint32_t k1) {
    int w = threadIdx.x >> 5, lane = threadIdx.x & 31;
    int c = blockIdx.x * 8 + w;
    if (c >= NCLS) return;
    float p = g_hcm[(size_t)c * 64 + lane] * W1[lane]
            + g_hcm[(size_t)c * 64 + lane + 32] * W1[lane + 32];
#pragma unroll
    for (int o = 16; o > 0; o >>= 1) p += __shfl_down_sync(0xffffffffu, p, o);
    if (lane == 0) {
        float logit = p + b1[0];
        float n = jr_normal(k0, k1, (uint32_t)c);
        out[c] = 1.f / (1.f + expf(-(logit + n)));
    }
}

// ------------------------- host -------------------------
extern "C" void kernel_launch(void* const* d_in, const int* in_sizes, int n_in,
                              void* d_out, int out_size) {
    (void)in_sizes; (void)n_in; (void)out_size;
    const int* lit_idx    = (const int*)d_in[0];
    const int* clause_idx = (const int*)d_in[1];
    const int* var_gid    = (const int*)d_in[2];
    const int* clause_gid = (const int*)d_in[3];
    const float* vq_W0 = (const float*)d_in[4];   const float* vq_b0 = (const float*)d_in[5];
    const float* vq_W1 = (const float*)d_in[6];   const float* vq_b1 = (const float*)d_in[7];
    const float* cm_W0 = (const float*)d_in[8];   const float* cm_b0 = (const float*)d_in[9];
    const float* cm_W1 = (const float*)d_in[10];  const float* cm_b1 = (const float*)d_in[11];
    const float* ug_W0 = (const float*)d_in[12];  const float* ug_b0 = (const float*)d_in[13];
    const float* ug_W1 = (const float*)d_in[14];  const float* ug_b1 = (const float*)d_in[15];
    const float* ug_W2 = (const float*)d_in[16];  const float* ug_b2 = (const float*)d_in[17];
    const float* co_W0 = (const float*)d_in[18];  const float* co_b0 = (const float*)d_in[19];
    const float* co_W1 = (const float*)d_in[20];  const float* co_b1 = (const float*)d_in[21];
    float* out = (float*)d_out;

    void *p_var, *p_clauses, *p_query, *p_cl, *p_hcm, *p_cdata, *p_unit, *p_h1, *p_h2, *p_nv;
    void *p_litdeg, *p_gsum, *p_gss;
    cudaGetSymbolAddress(&p_var, g_var);
    cudaGetSymbolAddress(&p_clauses, g_clauses);
    cudaGetSymbolAddress(&p_query, g_query);
    cudaGetSymbolAddress(&p_cl, g_cl);
    cudaGetSymbolAddress(&p_hcm, g_hcm);
    cudaGetSymbolAddress(&p_cdata, g_cdata);
    cudaGetSymbolAddress(&p_unit, g_unit);
    cudaGetSymbolAddress(&p_h1, g_h1);
    cudaGetSymbolAddress(&p_h2, g_h2);
    cudaGetSymbolAddress(&p_nv, g_nv);
    cudaGetSymbolAddress(&p_litdeg, g_litdeg);
    cudaGetSymbolAddress(&p_gsum, g_gsum);
    cudaGetSymbolAddress(&p_gss, g_gss);
    (void)p_cl; (void)p_query;

    // round keys: keys[r] = threefry_block(key(42)=(0,42), (0, r)) (partitionable split)
    uint32_t rk0[9], rk1[9];
    for (uint32_t r = 0; r < 9; r++) tf_block(0u, 42u, 0u, r, rk0[r], rk1[r]);

    // precompute: degrees, CSR, weights, graph starts, initial ones
    cudaMemsetAsync(p_litdeg, 0, NLIT * sizeof(int), 0);
    k_hist<<<(NNZT + 255) / 256, 256>>>(lit_idx);
    k_scan<<<1, 1024>>>();
    k_dw<<<(NLIT + 255) / 256, 256>>>();
    k_fill<<<(NNZT + 255) / 256, 256>>>(lit_idx, clause_idx);
    k_sortrows<<<(NLIT + 255) / 256, 256>>>();
    k_starts<<<1, 64>>>(var_gid, clause_gid);
    {
        size_t n = (size_t)NCLS * 64;
        k_initones<<<(unsigned)((n + 255) / 256), 256>>>();
    }

    float cscale = 1.f;
    for (int r = 0; r < 8; r++) {
        bool last = (r == 7);
        // v1 = [variables, noise]
        k_v1<<<(NVARS * 17 + 255) / 256, 256>>>(rk0[r], rk1[r]);
        // vq MLP -> query
        k_gemm<68, 64, true><<<(NVARS + 63) / 64, 256>>>((const float*)p_h1, vq_W0, vq_b0, (float*)p_nv, NVARS);
        k_gemm<64, 64, false><<<(NVARS + 63) / 64, 256>>>((const float*)p_nv, vq_W1, vq_b1, (float*)p_query, NVARS);
        // clause loss + grad halves of unit
        k_cv<<<(NCLS + 3) / 4, 256>>>(lit_idx);
        if (!last) k_gradunit<<<(NVARS + 3) / 4, 256>>>();
        // cm MLP
        k_cubuild<<<(NCLS * 32 + 255) / 256, 256>>>(cscale);
        k_gemm<128, 128, true><<<(NCLS + 63) / 64, 256>>>((const float*)p_cdata, cm_W0, cm_b0, (float*)p_hcm, NCLS);
        k_gemm<128, 128, false><<<(NCLS + 63) / 64, 256>>>((const float*)p_hcm, cm_W1, cm_b1, (float*)p_cdata, NCLS);
        // clause PairNorm + update
        cudaMemsetAsync(p_gsum, 0, NGR * 64 * sizeof(float), 0);
        cudaMemsetAsync(p_gss, 0, NGR * sizeof(float), 0);
        k_pnA<true><<<128, 256>>>(clause_gid);
        k_pnB<true><<<256, 256>>>(clause_gid);
        k_pnC<true><<<(NCLS * 64 + 255) / 256, 256>>>(clause_gid, 0.1f * cscale);
        if (!last) {
            // variables_loss halves of unit, ug MLP, var PairNorm + update
            k_VL<<<(NVARS + 3) / 4, 256>>>();
            k_gemm<256, 128, true><<<(NVARS + 63) / 64, 256>>>((const float*)p_unit, ug_W0, ug_b0, (float*)p_h1, NVARS);
            k_gemm<128, 128, true><<<(NVARS + 63) / 64, 256>>>((const float*)p_h1, ug_W1, ug_b1, (float*)p_h2, NVARS);
            k_gemm<128, 64, false><<<(NVARS + 63) / 64, 256>>>((const float*)p_h2, ug_W2, ug_b2, (float*)p_nv, NVARS);
            cudaMemsetAsync(p_gsum, 0, NGR * 64 * sizeof(float), 0);
            cudaMemsetAsync(p_gss, 0, NGR * sizeof(float), 0);
            k_pnA<false><<<64, 256>>>(var_gid);
            k_pnB<false><<<128, 256>>>(var_gid);
            k_pnC<false><<<(NVARS * 64 + 255) / 256, 256>>>(var_gid, 0.1f);
        }
        cscale = 0.2f;
    }
    // co MLP on final (unscaled) clauses + noise + sigmoid
    k_gemm<64, 64, true><<<(NCLS + 63) / 64, 256>>>((const float*)p_clauses, co_W0, co_b0, (float*)p_hcm, NCLS);
    k_logits<<<(NCLS + 7) / 8, 256>>>(co_W1, co_b1, out, rk0[8], rk1[8]);
}

// round 3
// speedup vs baseline: 1.0257x; 1.0257x over previous
#include <cuda_runtime.h>
#include <cstdint>
#include <cstddef>

#define NVARS 100000
#define NCLS  420000
#define NLIT  200000
#define NNZT  1260000
#define NGR   32
#define EPSN  1e-6f

// ------------------------- device scratch (no allocs) -------------------------
__device__ __align__(16) float g_var[(size_t)NVARS * 64];
__device__ __align__(16) float g_clauses[(size_t)NCLS * 64];   // unscaled new_clause state
__device__ __align__(16) float g_query[(size_t)NVARS * 64];
__device__ __align__(16) float g_cl[(size_t)NCLS * 64];        // exp(-cv)
__device__ __align__(16) float g_hcm[(size_t)NCLS * 128];      // cm hidden / co hidden
__device__ __align__(16) float g_cdata[(size_t)NCLS * 128];    // clause_data
__device__ __align__(16) float g_unit[(size_t)NVARS * 256];
__device__ __align__(16) float g_h1[(size_t)NVARS * 128];      // v1 [V,68] then ug hidden1
__device__ __align__(16) float g_h2[(size_t)NVARS * 128];
__device__ __align__(16) float g_nv[(size_t)NVARS * 64];       // vq hidden / ug out
__device__ float g_dw[NLIT];
__device__ float g_vdw[NVARS];
__device__ int   g_litdeg[NLIT];
__device__ int   g_csroff[NLIT + 1];
__device__ int   g_cursor[NLIT];
__device__ int   g_csrc[NNZT];
__device__ int   g_vstart[NGR + 1];
__device__ int   g_cstart[NGR + 1];
__device__ float g_gsum[NGR * 64];
__device__ float g_gss[NGR];

// ------------------------- f32x2 packed helpers -------------------------
__device__ __forceinline__ unsigned long long fma2(unsigned long long a, unsigned long long b,
                                                   unsigned long long c) {
    unsigned long long d;
    asm("fma.rn.f32x2 %0, %1, %2, %3;" : "=l"(d) : "l"(a), "l"(b), "l"(c));
    return d;
}
__device__ __forceinline__ unsigned long long pack2(float x) {
    unsigned long long d;
    asm("mov.b64 %0, {%1, %1};" : "=l"(d) : "f"(x));
    return d;
}
__device__ __forceinline__ float2 unpack2(unsigned long long v) {
    float lo, hi;
    asm("mov.b64 {%0, %1}, %2;" : "=f"(lo), "=f"(hi) : "l"(v));
    return make_float2(lo, hi);
}

// ------------------------- Threefry-2x32 (JAX exact) -------------------------
__host__ __device__ inline void tf_block(uint32_t k0, uint32_t k1, uint32_t x0, uint32_t x1,
                                         uint32_t& o0, uint32_t& o1) {
    uint32_t k2 = k0 ^ k1 ^ 0x1BD11BDAu;
    x0 += k0; x1 += k1;
#define TFR(r) { x0 += x1; x1 = (x1 << (r)) | (x1 >> (32 - (r))); x1 ^= x0; }
    TFR(13) TFR(15) TFR(26) TFR(6)  x0 += k1; x1 += k2 + 1u;
    TFR(17) TFR(29) TFR(16) TFR(24) x0 += k2; x1 += k0 + 2u;
    TFR(13) TFR(15) TFR(26) TFR(6)  x0 += k0; x1 += k1 + 3u;
    TFR(17) TFR(29) TFR(16) TFR(24) x0 += k1; x1 += k2 + 4u;
    TFR(13) TFR(15) TFR(26) TFR(6)  x0 += k2; x1 += k0 + 5u;
#undef TFR
    o0 = x0; o1 = x1;
}

// XLA ErfInv32 (Giles polynomial)
__device__ __forceinline__ float erfinv_f32(float x) {
    float w = -log1pf(-x * x);
    float p;
    if (w < 5.0f) {
        w -= 2.5f;
        p = 2.81022636e-08f;
        p = fmaf(p, w, 3.43273939e-07f);
        p = fmaf(p, w, -3.5233877e-06f);
        p = fmaf(p, w, -4.39150654e-06f);
        p = fmaf(p, w, 0.00021858087f);
        p = fmaf(p, w, -0.00125372503f);
        p = fmaf(p, w, -0.00417768164f);
        p = fmaf(p, w, 0.246640727f);
        p = fmaf(p, w, 1.50140941f);
    } else {
        w = sqrtf(w) - 3.0f;
        p = -0.000200214257f;
        p = fmaf(p, w, 0.000100950558f);
        p = fmaf(p, w, 0.00134934322f);
        p = fmaf(p, w, -0.00367342844f);
        p = fmaf(p, w, 0.00573950773f);
        p = fmaf(p, w, -0.0076224613f);
        p = fmaf(p, w, 0.00943887047f);
        p = fmaf(p, w, 1.00167406f);
        p = fmaf(p, w, 2.83297682f);
    }
    return p * x;
}

__device__ __forceinline__ float jr_normal(uint32_t k0, uint32_t k1, uint32_t idx) {
    uint32_t a, b;
    tf_block(k0, k1, 0u, idx, a, b);
    uint32_t bits = a ^ b;
    float f = __uint_as_float(0x3F800000u | (bits >> 9)) - 1.0f;
    float u = fmaxf(fmaf(f, 2.0f, -0.99999994f), -0.99999994f);
    return 1.41421356f * erfinv_f32(u);
}

// ------------------------- GEMM: Y[M,N] = act(X[M,K] @ W[K,N] + b) -------------------------
// 64-row tiles, 256 threads, 4 rows x TN cols per thread, packed f32x2 FMA.
template<int K, int N, bool RELU, bool CAT2>
__global__ __launch_bounds__(256)
void k_gemm(const float* __restrict__ X, const float* __restrict__ Xb2,
            float sa, float sb,
            const float* __restrict__ W,
            const float* __restrict__ bias, float* __restrict__ Y, int M) {
    constexpr int TN = N / 16;
    constexpr int TP = TN / 2;
    __shared__ float Xs[16][68];
    __shared__ float Ws[16][N];
    int t = threadIdx.x;
    int m0 = blockIdx.x * 64;
    int tx = t & 15, ty = t >> 4;
    unsigned long long acc[4][TP];
#pragma unroll
    for (int i = 0; i < 4; i++)
#pragma unroll
        for (int j = 0; j < TP; j++) acc[i][j] = 0ULL;
    float bs[TN];
#pragma unroll
    for (int j = 0; j < TN; j++) bs[j] = bias[tx * TN + j];

    int r = t >> 2, kg = t & 3;
    bool rok = (m0 + r) < M;
    constexpr int KT = (K + 15) / 16;
    constexpr int NF4 = N / 4;
    for (int kt = 0; kt < KT; kt++) {
        int k0 = kt * 16;
        float4 xv = make_float4(0.f, 0.f, 0.f, 0.f);
        int kk = k0 + kg * 4;
        if (CAT2) {
            if (rok) {
                if (kk < 64) {
                    xv = *(const float4*)(X + (size_t)(m0 + r) * 64 + kk);
                    xv.x *= sa; xv.y *= sa; xv.z *= sa; xv.w *= sa;
                } else if (kk < K) {
                    xv = *(const float4*)(Xb2 + (size_t)(m0 + r) * 64 + (kk - 64));
                    xv.x *= sb; xv.y *= sb; xv.z *= sb; xv.w *= sb;
                }
            }
        } else {
            if (rok && kk < K) xv = *(const float4*)(X + (size_t)(m0 + r) * K + kk);
        }
        Xs[kg * 4 + 0][r] = xv.x;
        Xs[kg * 4 + 1][r] = xv.y;
        Xs[kg * 4 + 2][r] = xv.z;
        Xs[kg * 4 + 3][r] = xv.w;
#pragma unroll
        for (int q = t; q < 16 * NF4; q += 256) {
            int k = q / NF4, n4 = q % NF4;
            float4 wv = make_float4(0.f, 0.f, 0.f, 0.f);
            if (k0 + k < K) wv = *(const float4*)(W + (size_t)(k0 + k) * N + n4 * 4);
            *((float4*)&Ws[k][0] + n4) = wv;
        }
        __syncthreads();
#pragma unroll
        for (int k = 0; k < 16; k++) {
            float4 a = *(const float4*)&Xs[k][ty * 4];
            unsigned long long av0 = pack2(a.x), av1 = pack2(a.y);
            unsigned long long av2 = pack2(a.z), av3 = pack2(a.w);
            unsigned long long bv[TP];
            const unsigned long long* wrow = (const unsigned long long*)&Ws[k][tx * TN];
#pragma unroll
            for (int j = 0; j < TP; j++) bv[j] = wrow[j];
#pragma unroll
            for (int j = 0; j < TP; j++) {
                acc[0][j] = fma2(av0, bv[j], acc[0][j]);
                acc[1][j] = fma2(av1, bv[j], acc[1][j]);
                acc[2][j] = fma2(av2, bv[j], acc[2][j]);
                acc[3][j] = fma2(av3, bv[j], acc[3][j]);
            }
        }
        __syncthreads();
    }
#pragma unroll
    for (int i = 0; i < 4; i++) {
        int row = m0 + ty * 4 + i;
        if (row < M) {
#pragma unroll
            for (int j4 = 0; j4 < TN / 4; j4++) {
                float2 u0 = unpack2(acc[i][j4 * 2 + 0]);
                float2 u1 = unpack2(acc[i][j4 * 2 + 1]);
                float4 o;
                o.x = u0.x + bs[j4 * 4 + 0];
                o.y = u0.y + bs[j4 * 4 + 1];
                o.z = u1.x + bs[j4 * 4 + 2];
                o.w = u1.y + bs[j4 * 4 + 3];
                if (RELU) {
                    o.x = fmaxf(o.x, 0.f); o.y = fmaxf(o.y, 0.f);
                    o.z = fmaxf(o.z, 0.f); o.w = fmaxf(o.w, 0.f);
                }
                *((float4*)(Y + (size_t)row * N + tx * TN) + j4) = o;
            }
        }
    }
}

// ------------------------- precompute kernels -------------------------
__global__ void k_hist(const int* __restrict__ lit_idx) {
    int e = blockIdx.x * blockDim.x + threadIdx.x;
    if (e < NNZT) atomicAdd(&g_litdeg[lit_idx[e]], 1);
}

__global__ void k_scan() {
    __shared__ int warps[32];
    __shared__ int s_carry;
    int t = threadIdx.x;
    if (t == 0) s_carry = 0;
    __syncthreads();
    const int NCHUNK = (NLIT + 1023) / 1024;
    for (int ch = 0; ch < NCHUNK; ch++) {
        int idx = ch * 1024 + t;
        int v = (idx < NLIT) ? g_litdeg[idx] : 0;
        int x = v;
#pragma unroll
        for (int o = 1; o < 32; o <<= 1) {
            int y = __shfl_up_sync(0xffffffffu, x, o);
            if ((t & 31) >= o) x += y;
        }
        if ((t & 31) == 31) warps[t >> 5] = x;
        __syncthreads();
        if (t < 32) {
            int y = warps[t];
#pragma unroll
            for (int o = 1; o < 32; o <<= 1) {
                int z = __shfl_up_sync(0xffffffffu, y, o);
                if (t >= o) y += z;
            }
            warps[t] = y;
        }
        __syncthreads();
        int incl = x + ((t >= 32) ? warps[(t >> 5) - 1] : 0);
        int excl = incl - v;
        if (idx < NLIT) g_csroff[idx] = s_carry + excl;
        int total = warps[31];
        __syncthreads();
        if (t == 0) s_carry += total;
        __syncthreads();
    }
    if (t == 0) g_csroff[NLIT] = s_carry;
}

__global__ void k_dw() {
    int i = blockIdx.x * blockDim.x + threadIdx.x;
    if (i < NLIT) {
        g_dw[i] = rsqrtf(fmaxf((float)g_litdeg[i], 1.f));
        g_cursor[i] = 0;
    }
    if (i < NVARS)
        g_vdw[i] = 4.f * rsqrtf(fmaxf((float)(g_litdeg[i] + g_litdeg[i + NVARS]), 1.f));
}

__global__ void k_fill(const int* __restrict__ lit_idx, const int* __restrict__ clause_idx) {
    int e = blockIdx.x * blockDim.x + threadIdx.x;
    if (e >= NNZT) return;
    int l = lit_idx[e];
    int pos = atomicAdd(&g_cursor[l], 1);
    g_csrc[g_csroff[l] + pos] = clause_idx[e];
}

__global__ void k_sortrows() {
    int l = blockIdx.x * blockDim.x + threadIdx.x;
    if (l >= NLIT) return;
    int b = g_csroff[l], n = g_csroff[l + 1] - b;
    if (n <= 1 || n > 48) return;
    int a[48];
    for (int i = 0; i < n; i++) a[i] = g_csrc[b + i];
    for (int i = 1; i < n; i++) {
        int key = a[i], j = i - 1;
        while (j >= 0 && a[j] > key) { a[j + 1] = a[j]; j--; }
        a[j + 1] = key;
    }
    for (int i = 0; i < n; i++) g_csrc[b + i] = a[i];
}

__global__ void k_starts(const int* __restrict__ vgid, const int* __restrict__ cgid) {
    int g = threadIdx.x;
    if (g > NGR) return;
    int lo = 0, hi = NVARS;
    while (lo < hi) { int mid = (lo + hi) >> 1; if (vgid[mid] < g) lo = mid + 1; else hi = mid; }
    g_vstart[g] = lo;
    lo = 0; hi = NCLS;
    while (lo < hi) { int mid = (lo + hi) >> 1; if (cgid[mid] < g) lo = mid + 1; else hi = mid; }
    g_cstart[g] = lo;
}

__global__ void k_initones() {
    size_t i = (size_t)blockIdx.x * blockDim.x + threadIdx.x;
    size_t nv = (size_t)NVARS * 64, nc = (size_t)NCLS * 64;
    if (i < nv) g_var[i] = 1.f;
    if (i < nc) g_clauses[i] = 1.f;
}

// ------------------------- per-round kernels -------------------------
__global__ void k_v1(uint32_t k0, uint32_t k1) {
    int idx = blockIdx.x * blockDim.x + threadIdx.x;
    if (idx >= NVARS * 17) return;
    int v = idx / 17, c4 = idx % 17;
    if (c4 < 16) {
        float4 val = *(const float4*)(g_var + (size_t)v * 64 + c4 * 4);
        *(float4*)(g_h1 + (size_t)v * 68 + c4 * 4) = val;
    } else {
        float4 o;
        o.x = jr_normal(k0, k1, (uint32_t)(v * 4 + 0));
        o.y = jr_normal(k0, k1, (uint32_t)(v * 4 + 1));
        o.z = jr_normal(k0, k1, (uint32_t)(v * 4 + 2));
        o.w = jr_normal(k0, k1, (uint32_t)(v * 4 + 3));
        *(float4*)(g_h1 + (size_t)v * 68 + 64) = o;
    }
}

// cl = exp(-sum softplus(x_j)) = prod_j 1/(1+exp(x_j))
__global__ void k_cv(const int* __restrict__ lit_idx) {
    int t = threadIdx.x;
    int c = blockIdx.x * 4 + (t >> 6);
    int f = t & 63;
    if (c >= NCLS) return;
    float p = 1.f;
#pragma unroll
    for (int j = 0; j < 3; j++) {
        int l = lit_idx[3 * c + j];
        int v = (l >= NVARS) ? (l - NVARS) : l;
        float q = g_query[(size_t)v * 64 + f];
        float x = (l >= NVARS) ? -q : q;
        p *= 1.f + __expf(x);
    }
    g_cl[(size_t)c * 64 + f] = __fdividef(1.f, p);
}

__global__ void k_gradunit() {
    int t = threadIdx.x;
    int v = blockIdx.x * 4 + (t >> 6);
    int f = t & 63;
    if (v >= NVARS) return;
    float S1 = 0.f, S2 = 0.f;
    int b0 = g_csroff[v], e0 = g_csroff[v + 1];
    for (int i = b0; i < e0; i++) S1 += g_cl[(size_t)g_csrc[i] * 64 + f];
    int b1 = g_csroff[NVARS + v], e1 = g_csroff[NVARS + v + 1];
    for (int i = b1; i < e1; i++) S2 += g_cl[(size_t)g_csrc[i] * 64 + f];
    float q = g_query[(size_t)v * 64 + f];
    float sp = 1.f / (1.f + expf(-q));
    float sn = 1.f / (1.f + expf(q));
    float qg = fmaf(-S1, sp, S2 * sn);
    g_unit[(size_t)v * 256 + f] = qg * g_vdw[v];
    g_unit[(size_t)v * 256 + 64 + f] = g_var[(size_t)v * 64 + f];
}

__global__ void k_VL() {
    int t = threadIdx.x;
    int v = blockIdx.x * 4 + (t >> 6);
    int f = t & 63;
    if (v >= NVARS) return;
    float T1 = 0.f, T2 = 0.f;
    int b0 = g_csroff[v], e0 = g_csroff[v + 1];
    for (int i = b0; i < e0; i++) T1 += g_cdata[(size_t)g_csrc[i] * 128 + f];
    int b1 = g_csroff[NVARS + v], e1 = g_csroff[NVARS + v + 1];
    for (int i = b1; i < e1; i++) T2 += g_cdata[(size_t)g_csrc[i] * 128 + f];
    g_unit[(size_t)v * 256 + 128 + f] = T1 * g_dw[v];
    g_unit[(size_t)v * 256 + 192 + f] = T2 * g_dw[v + NVARS];
}

// ------------------------- PairNorm (3 passes) -------------------------
template<bool CL>
__global__ void k_pnA(const int* __restrict__ gid) {
    const float* x = CL ? (g_cdata + 64) : g_nv;
    const int stride = CL ? 128 : 64;
    const int M = CL ? NCLS : NVARS;
    int G = gridDim.x;
    int chunk = (M + G - 1) / G;
    int start = blockIdx.x * chunk, end = min(M, start + chunk);
    int f = threadIdx.x & 63, rl = threadIdx.x >> 6;
    float acc = 0.f; int curg = -1;
    for (int r = start + rl; r < end; r += 4) {
        int g = gid[r];
        if (g != curg) {
            if (curg >= 0) atomicAdd(&g_gsum[curg * 64 + f], acc);
            acc = 0.f; curg = g;
        }
        acc += x[(size_t)r * stride + f];
    }
    if (curg >= 0) atomicAdd(&g_gsum[curg * 64 + f], acc);
}

template<bool CL>
__global__ void k_pnB(const int* __restrict__ gid) {
    const float* x = CL ? (g_cdata + 64) : g_nv;
    const int stride = CL ? 128 : 64;
    const int M = CL ? NCLS : NVARS;
    const int* starts = CL ? g_cstart : g_vstart;
    int G = gridDim.x;
    int chunk = (M + G - 1) / G;
    int start = blockIdx.x * chunk, end = min(M, start + chunk);
    int w = threadIdx.x >> 5, lane = threadIdx.x & 31;
    float acc = 0.f; int curg = -1;
    for (int r = start + w; r < end; r += 8) {
        int g = gid[r];
        float cnt = fmaxf((float)(starts[g + 1] - starts[g]), 1.f);
        float m1 = g_gsum[g * 64 + lane] / cnt;
        float m2 = g_gsum[g * 64 + lane + 32] / cnt;
        float d1 = x[(size_t)r * stride + lane] - m1;
        float d2 = x[(size_t)r * stride + lane + 32] - m2;
        float p = d1 * d1 + d2 * d2;
#pragma unroll
        for (int o = 16; o > 0; o >>= 1) p += __shfl_down_sync(0xffffffffu, p, o);
        if (lane == 0) {
            p *= (1.f / 64.f);
            if (g != curg) {
                if (curg >= 0) atomicAdd(&g_gss[curg], acc);
                acc = 0.f; curg = g;
            }
            acc += p;
        }
    }
    if (lane == 0 && curg >= 0) atomicAdd(&g_gss[curg], acc);
}

template<bool CL>
__global__ void k_pnC(const int* __restrict__ gid, float oldscale) {
    const float* x = CL ? (g_cdata + 64) : g_nv;
    const int stride = CL ? 128 : 64;
    const int M = CL ? NCLS : NVARS;
    const int* starts = CL ? g_cstart : g_vstart;
    float* out = CL ? g_clauses : g_var;
    int i = blockIdx.x * blockDim.x + threadIdx.x;
    if (i >= M * 64) return;
    int r = i >> 6, f = i & 63;
    int g = gid[r];
    float cnt = fmaxf((float)(starts[g + 1] - starts[g]), 1.f);
    float mean = g_gsum[g * 64 + f] / cnt;
    float var = g_gss[g] / cnt;
    float val = 0.25f * (x[(size_t)r * stride + f] - mean) * rsqrtf(var + EPSN);
    out[(size_t)r * 64 + f] = val + oldscale * out[(size_t)r * 64 + f];
}

// ------------------------- final logits + noise + sigmoid -------------------------
__global__ void k_logits(const float* __restrict__ W1, const float* __restrict__ b1,
                         float* __restrict__ out, uint32_t k0, uint32_t k1) {
    int w = threadIdx.x >> 5, lane = threadIdx.x & 31;
    int c = blockIdx.x * 8 + w;
    if (c >= NCLS) return;
    float p = g_hcm[(size_t)c * 64 + lane] * W1[lane]
            + g_hcm[(size_t)c * 64 + lane + 32] * W1[lane + 32];
#pragma unroll
    for (int o = 16; o > 0; o >>= 1) p += __shfl_down_sync(0xffffffffu, p, o);
    if (lane == 0) {
        float logit = p + b1[0];
        float n = jr_normal(k0, k1, (uint32_t)c);
        out[c] = 1.f / (1.f + expf(-(logit + n)));
    }
}

// ------------------------- host -------------------------
extern "C" void kernel_launch(void* const* d_in, const int* in_sizes, int n_in,
                              void* d_out, int out_size) {
    (void)in_sizes; (void)n_in; (void)out_size;
    const int* lit_idx    = (const int*)d_in[0];
    const int* clause_idx = (const int*)d_in[1];
    const int* var_gid    = (const int*)d_in[2];
    const int* clause_gid = (const int*)d_in[3];
    const float* vq_W0 = (const float*)d_in[4];   const float* vq_b0 = (const float*)d_in[5];
    const float* vq_W1 = (const float*)d_in[6];   const float* vq_b1 = (const float*)d_in[7];
    const float* cm_W0 = (const float*)d_in[8];   const float* cm_b0 = (const float*)d_in[9];
    const float* cm_W1 = (const float*)d_in[10];  const float* cm_b1 = (const float*)d_in[11];
    const float* ug_W0 = (const float*)d_in[12];  const float* ug_b0 = (const float*)d_in[13];
    const float* ug_W1 = (const float*)d_in[14];  const float* ug_b1 = (const float*)d_in[15];
    const float* ug_W2 = (const float*)d_in[16];  const float* ug_b2 = (const float*)d_in[17];
    const float* co_W0 = (const float*)d_in[18];  const float* co_b0 = (const float*)d_in[19];
    const float* co_W1 = (const float*)d_in[20];  const float* co_b1 = (const float*)d_in[21];
    float* out = (float*)d_out;

    void *p_var, *p_clauses, *p_query, *p_cl, *p_hcm, *p_cdata, *p_unit, *p_h1, *p_h2, *p_nv;
    void *p_litdeg, *p_gsum, *p_gss;
    cudaGetSymbolAddress(&p_var, g_var);
    cudaGetSymbolAddress(&p_clauses, g_clauses);
    cudaGetSymbolAddress(&p_query, g_query);
    cudaGetSymbolAddress(&p_cl, g_cl);
    cudaGetSymbolAddress(&p_hcm, g_hcm);
    cudaGetSymbolAddress(&p_cdata, g_cdata);
    cudaGetSymbolAddress(&p_unit, g_unit);
    cudaGetSymbolAddress(&p_h1, g_h1);
    cudaGetSymbolAddress(&p_h2, g_h2);
    cudaGetSymbolAddress(&p_nv, g_nv);
    cudaGetSymbolAddress(&p_litdeg, g_litdeg);
    cudaGetSymbolAddress(&p_gsum, g_gsum);
    cudaGetSymbolAddress(&p_gss, g_gss);

    uint32_t rk0[9], rk1[9];
    for (uint32_t r = 0; r < 9; r++) tf_block(0u, 42u, 0u, r, rk0[r], rk1[r]);

    cudaMemsetAsync(p_litdeg, 0, NLIT * sizeof(int), 0);
    k_hist<<<(NNZT + 255) / 256, 256>>>(lit_idx);
    k_scan<<<1, 1024>>>();
    k_dw<<<(NLIT + 255) / 256, 256>>>();
    k_fill<<<(NNZT + 255) / 256, 256>>>(lit_idx, clause_idx);
    k_sortrows<<<(NLIT + 255) / 256, 256>>>();
    k_starts<<<1, 64>>>(var_gid, clause_gid);
    {
        size_t n = (size_t)NCLS * 64;
        k_initones<<<(unsigned)((n + 255) / 256), 256>>>();
    }

    float cscale = 1.f;
    for (int r = 0; r < 8; r++) {
        bool last = (r == 7);
        k_v1<<<(NVARS * 17 + 255) / 256, 256>>>(rk0[r], rk1[r]);
        k_gemm<68, 64, true, false><<<(NVARS + 63) / 64, 256>>>((const float*)p_h1, nullptr, 1.f, 1.f, vq_W0, vq_b0, (float*)p_nv, NVARS);
        k_gemm<64, 64, false, false><<<(NVARS + 63) / 64, 256>>>((const float*)p_nv, nullptr, 1.f, 1.f, vq_W1, vq_b1, (float*)p_query, NVARS);
        k_cv<<<(NCLS + 3) / 4, 256>>>(lit_idx);
        if (!last) k_gradunit<<<(NVARS + 3) / 4, 256>>>();
        // cm MLP: first layer reads [cscale*clauses, 4*cl] via concat loader
        k_gemm<128, 128, true, true><<<(NCLS + 63) / 64, 256>>>((const float*)p_clauses, (const float*)p_cl, cscale, 4.f, cm_W0, cm_b0, (float*)p_hcm, NCLS);
        k_gemm<128, 128, false, false><<<(NCLS + 63) / 64, 256>>>((const float*)p_hcm, nullptr, 1.f, 1.f, cm_W1, cm_b1, (float*)p_cdata, NCLS);
        cudaMemsetAsync(p_gsum, 0, NGR * 64 * sizeof(float), 0);
        cudaMemsetAsync(p_gss, 0, NGR * sizeof(float), 0);
        k_pnA<true><<<128, 256>>>(clause_gid);
        k_pnB<true><<<256, 256>>>(clause_gid);
        k_pnC<true><<<(NCLS * 64 + 255) / 256, 256>>>(clause_gid, 0.1f * cscale);
        if (!last) {
            k_VL<<<(NVARS + 3) / 4, 256>>>();
            k_gemm<256, 128, true, false><<<(NVARS + 63) / 64, 256>>>((const float*)p_unit, nullptr, 1.f, 1.f, ug_W0, ug_b0, (float*)p_h1, NVARS);
            k_gemm<128, 128, true, false><<<(NVARS + 63) / 64, 256>>>((const float*)p_h1, nullptr, 1.f, 1.f, ug_W1, ug_b1, (float*)p_h2, NVARS);
            k_gemm<128, 64, false, false><<<(NVARS + 63) / 64, 256>>>((const float*)p_h2, nullptr, 1.f, 1.f, ug_W2, ug_b2, (float*)p_nv, NVARS);
            cudaMemsetAsync(p_gsum, 0, NGR * 64 * sizeof(float), 0);
            cudaMemsetAsync(p_gss, 0, NGR * sizeof(float), 0);
            k_pnA<false><<<64, 256>>>(var_gid);
            k_pnB<false><<<128, 256>>>(var_gid);
            k_pnC<false><<<(NVARS * 64 + 255) / 256, 256>>>(var_gid, 0.1f);
        }
        cscale = 0.2f;
    }
    k_gemm<64, 64, true, false><<<(NCLS + 63) / 64, 256>>>((const float*)p_clauses, nullptr, 1.f, 1.f, co_W0, co_b0, (float*)p_hcm, NCLS);
    k_logits<<<(NCLS + 7) / 8, 256>>>(co_W1, co_b1, out, rk0[8], rk1[8]);
}